// round 9
// baseline (speedup 1.0000x reference)
#include <cuda_runtime.h>
#include <cstdint>

#define BB 64
#define TT 2048
#define VV 256
#define HH 64
#define NHH 4
#define HDD 16
#define NLVL 2
#define G4H 256
#define NROWS (BB * TT)   // 131072

typedef unsigned long long ull;

// ---------------- scratch ----------------
__device__ float g_table[VV * G4H];             // 256 KB
__device__ float g_bufA[(size_t)NROWS * HH];    // 32 MB
__device__ float g_bufB[(size_t)NROWS * HH];    // 32 MB
__device__ float g_qkv[(size_t)NROWS * 3 * HH]; // 96 MB
__device__ float g_att[(size_t)NROWS * HH];     // 32 MB

// ---------------- packed f32x2 helpers (sm_103a) ----------------
__device__ __forceinline__ ull fma2(ull a, ull b, ull c) {
    ull d; asm("fma.rn.f32x2 %0,%1,%2,%3;" : "=l"(d) : "l"(a), "l"(b), "l"(c)); return d;
}
__device__ __forceinline__ ull add2(ull a, ull b) {
    ull d; asm("add.rn.f32x2 %0,%1,%2;" : "=l"(d) : "l"(a), "l"(b)); return d;
}
__device__ __forceinline__ float hadd2(ull a) {
    float lo, hi; asm("mov.b64 {%0,%1},%2;" : "=f"(lo), "=f"(hi) : "l"(a)); return lo + hi;
}
__device__ __forceinline__ ull dup2(float x) {
    ull d; asm("mov.b64 %0,{%1,%1};" : "=l"(d) : "f"(x)); return d;
}
__device__ __forceinline__ float2 unpk2(ull a) {
    float2 r; asm("mov.b64 {%0,%1},%2;" : "=f"(r.x), "=f"(r.y) : "l"(a)); return r;
}
// hardware tanh (MUFU.TANH)
__device__ __forceinline__ float htanh(float x) {
    float r; asm("tanh.approx.f32 %0,%1;" : "=f"(r) : "f"(x)); return r;
}

// ---------------- 1) vocab -> gate-preact table ----------------
__global__ void __launch_bounds__(G4H) table_kernel(
    const float* __restrict__ emb, const float* __restrict__ w_ih,
    const float* __restrict__ b_ih, const float* __restrict__ b_hh)
{
    __shared__ __align__(16) float e[HH];
    const int v = blockIdx.x;
    const int j = threadIdx.x;
    if (j < HH) e[j] = emb[v * HH + j];
    __syncthreads();
    float acc = b_ih[j] + b_hh[j];
    const float* wr = w_ih + j * HH;
#pragma unroll
    for (int k = 0; k < HH; k++) acc += e[k] * wr[k];
    g_table[v * G4H + j] = acc;
}

// ---------------- 2) LSTM (identical to R8-passing version) ----------------
__global__ void __launch_bounds__(256) lstm_kernel(
    const int* __restrict__ x, const float* __restrict__ w_hh,
    float* __restrict__ hout)
{
    const int b = blockIdx.x;
    const int tid = threadIdx.x;
    const int j = tid >> 2;
    const int q = tid & 3;

    __shared__ int x_sh[TT];
    __shared__ __align__(16) float h_sh[2][HH];

    for (int i = tid; i < TT; i += 256) x_sh[i] = x[b * TT + i];

    const int r = q * HH + j;
    ull w2[32];
    const ulonglong2* wp = (const ulonglong2*)(w_hh + r * HH);
#pragma unroll
    for (int k = 0; k < 16; k++) {
        ulonglong2 t = wp[k];
        w2[2 * k] = t.x; w2[2 * k + 1] = t.y;
    }
    if (tid < HH) { h_sh[0][tid] = 0.0f; }
    float c = 0.0f;

    const float sA = (q == 2) ? 1.0f : 0.5f;
    const float aA = (q == 2) ? 1.0f : 0.5f;
    const float bA = (q == 2) ? 0.0f : 0.5f;

    __syncthreads();

    float xw = g_table[x_sh[0] * G4H + r];

    for (int t = 0; t < TT; t++) {
        float xw_next = 0.0f;
        if (t + 1 < TT) xw_next = g_table[x_sh[t + 1] * G4H + r];

        const ulonglong2* h2 = (const ulonglong2*)h_sh[t & 1];
        ull a0 = 0ull, a1 = 0ull, a2 = 0ull, a3 = 0ull;
#pragma unroll
        for (int k = 0; k < 16; k += 2) {
            ulonglong2 p = h2[k];
            ulonglong2 s = h2[k + 1];
            a0 = fma2(p.x, w2[2 * k + 0], a0);
            a1 = fma2(p.y, w2[2 * k + 1], a1);
            a2 = fma2(s.x, w2[2 * k + 2], a2);
            a3 = fma2(s.y, w2[2 * k + 3], a3);
        }
        float pre = xw + hadd2(add2(add2(a0, a1), add2(a2, a3)));

        float act = aA * htanh(sA * pre) + bA;

        float act_f = __shfl_down_sync(0xffffffffu, act, 1);
        float act_g = __shfl_down_sync(0xffffffffu, act, 2);
        float act_o = __shfl_down_sync(0xffffffffu, act, 3);

        c = act_f * c + act * act_g;
        float hn = act_o * htanh(c);

        if (q == 0) {
            h_sh[(t + 1) & 1][j] = hn;
            hout[((size_t)b * TT + t) * HH + j] = hn;
        }
        __syncthreads();
        xw = xw_next;
    }
}

// ---------------- 3) K-split GEMM: lane pair (s=0,1) splits K=64 ----------
// Block = J*G*2 threads; R = 64 rows per block; thread (j, g, s).
template<int J, int G>
__global__ void __launch_bounds__(J * G * 2) gemm_split_kernel(
    const float* __restrict__ A, const float* __restrict__ W,
    const float* __restrict__ bias, float* __restrict__ C)
{
    __shared__ __align__(16) float Ash[64][HH];   // 16 KB
    const int tid = threadIdx.x;
    constexpr int NTHR = J * G * 2;
    const size_t row0 = (size_t)blockIdx.x * 64;

    for (int i4 = tid; i4 < 64 * (HH / 4); i4 += NTHR)
        ((float4*)Ash)[i4] = ((const float4*)(A + row0 * HH))[i4];

    const int s  = tid & 1;          // K-half
    const int jg = tid >> 1;
    const int j  = jg % J;           // output column
    const int g  = jg / J;           // row group

    // 32 weights (this K-half) as 16 packed f32x2
    ull w2[16];
    const ulonglong2* wp = (const ulonglong2*)(W + j * HH + s * 32);
#pragma unroll
    for (int k = 0; k < 8; k++) {
        ulonglong2 t = wp[k];
        w2[2 * k] = t.x; w2[2 * k + 1] = t.y;
    }
    const float bj = bias[j];
    __syncthreads();

    constexpr int RT = 64 / G;
#pragma unroll
    for (int t0 = 0; t0 < RT; t0 += 16) {
        ull acc[16];
#pragma unroll
        for (int u = 0; u < 16; u++) acc[u] = 0ull;
#pragma unroll
        for (int u = 0; u < 16; u++) {
            const int r = (t0 + u) * G + g;
            const ulonglong2* ap = (const ulonglong2*)Ash[r] + s * 8;  // this K-half
#pragma unroll
            for (int p = 0; p < 8; p++) {
                ulonglong2 av = ap[p];
                acc[u] = fma2(av.x, w2[2 * p], acc[u]);
                acc[u] = fma2(av.y, w2[2 * p + 1], acc[u]);
            }
        }
#pragma unroll
        for (int u = 0; u < 16; u++) {
            float part = hadd2(acc[u]);
            float oth  = __shfl_down_sync(0xffffffffu, part, 1);
            if (s == 0)
                C[(row0 + (size_t)((t0 + u) * G + g)) * J + j] = bj + part + oth;
        }
    }
}

// ---------------- 4) attention: single-pass softmax (identical to R8) ----------
__global__ void __launch_bounds__(64) attn_kernel(
    const float* __restrict__ qkv, float* __restrict__ attout)
{
    const int n  = blockIdx.x >> 2;
    const int hh = blockIdx.x & 3;
    const int l  = threadIdx.x;

    __shared__ __align__(16) float k_sh[64][HDD];
    __shared__ __align__(16) float v_sh[64][HDD];

    const float* rowp = qkv + ((size_t)l * TT + n) * (3 * HH) + hh * HDD;
    ull q2[8];
#pragma unroll
    for (int p = 0; p < 4; p++) {
        ulonglong2 tq = ((const ulonglong2*)rowp)[p];
        q2[2 * p] = tq.x; q2[2 * p + 1] = tq.y;
        ((float4*)k_sh[l])[p] = ((const float4*)(rowp + HH))[p];
        ((float4*)v_sh[l])[p] = ((const float4*)(rowp + 2 * HH))[p];
    }
    __syncthreads();

    float sum = 0.0f;
    ull o2[8];
#pragma unroll
    for (int p = 0; p < 8; p++) o2[p] = 0ull;

#pragma unroll 4
    for (int m = 0; m < 64; m++) {
        const ulonglong2* kp = (const ulonglong2*)k_sh[m];
        ull acc = 0ull;
#pragma unroll
        for (int p = 0; p < 4; p++) {
            ulonglong2 kv = kp[p];
            acc = fma2(q2[2 * p], kv.x, acc);
            acc = fma2(q2[2 * p + 1], kv.y, acc);
        }
        float pm = __expf(hadd2(acc) * 0.25f);
        sum += pm;
        ull pm2 = dup2(pm);
        const ulonglong2* vp = (const ulonglong2*)v_sh[m];
#pragma unroll
        for (int p = 0; p < 4; p++) {
            ulonglong2 vv = vp[p];
            o2[2 * p]     = fma2(pm2, vv.x, o2[2 * p]);
            o2[2 * p + 1] = fma2(pm2, vv.y, o2[2 * p + 1]);
        }
    }
    const float inv = __fdividef(1.0f, sum);

    float* op = attout + ((size_t)l * TT + n) * HH + hh * HDD;
#pragma unroll
    for (int p = 0; p < 4; p++) {
        float2 e0 = unpk2(o2[2 * p]);
        float2 e1 = unpk2(o2[2 * p + 1]);
        float4 t;
        t.x = e0.x * inv; t.y = e0.y * inv;
        t.z = e1.x * inv; t.w = e1.y * inv;
        ((float4*)op)[p] = t;
    }
}

// ---------------- 5) LayerNorm + vocab FC, K-split (512 threads) ----------
__global__ void __launch_bounds__(512) lnfc_kernel(
    const float* __restrict__ hin,
    const float* __restrict__ lng, const float* __restrict__ lnb,
    const float* __restrict__ fcw, const float* __restrict__ fcb,
    float* __restrict__ out)
{
    constexpr int RB = 32;
    __shared__ __align__(16) float hn[RB][HH];
    const int tid = threadIdx.x, warp = tid >> 5, lane = tid & 31;
    const size_t row0 = (size_t)blockIdx.x * RB;

    // LN phase: 16 warps, 2 rows each
    for (int rr = warp; rr < RB; rr += 16) {
        const float* hp = hin + (row0 + rr) * HH;
        float a0 = hp[lane], a1 = hp[lane + 32];
        float sm = a0 + a1, sq = a0 * a0 + a1 * a1;
#pragma unroll
        for (int off = 16; off; off >>= 1) {
            sm += __shfl_xor_sync(0xffffffffu, sm, off);
            sq += __shfl_xor_sync(0xffffffffu, sq, off);
        }
        float mu  = sm * (1.0f / HH);
        float var = sq * (1.0f / HH) - mu * mu;
        float rs  = rsqrtf(var + 1e-5f);
        hn[rr][lane]      = (a0 - mu) * rs * lng[lane]      + lnb[lane];
        hn[rr][lane + 32] = (a1 - mu) * rs * lng[lane + 32] + lnb[lane + 32];
    }
    __syncthreads();

    // FC phase: thread (j, s) — j = vocab col, s = K-half
    const int s = tid & 1;
    const int j = tid >> 1;         // 0..255
    ull w2[16];
    const ulonglong2* wp = (const ulonglong2*)(fcw + j * HH + s * 32);
#pragma unroll
    for (int k = 0; k < 8; k++) {
        ulonglong2 t = wp[k];
        w2[2 * k] = t.x; w2[2 * k + 1] = t.y;
    }
    const float bj = fcb[j];
#pragma unroll
    for (int half = 0; half < 2; half++) {
        ull acc[16];
#pragma unroll
        for (int u = 0; u < 16; u++) acc[u] = 0ull;
#pragma unroll
        for (int u = 0; u < 16; u++) {
            const ulonglong2* ap = (const ulonglong2*)hn[half * 16 + u] + s * 8;
#pragma unroll
            for (int p = 0; p < 8; p++) {
                ulonglong2 av = ap[p];
                acc[u] = fma2(av.x, w2[2 * p], acc[u]);
                acc[u] = fma2(av.y, w2[2 * p + 1], acc[u]);
            }
        }
#pragma unroll
        for (int u = 0; u < 16; u++) {
            float part = hadd2(acc[u]);
            float oth  = __shfl_down_sync(0xffffffffu, part, 1);
            if (s == 0)
                out[(row0 + half * 16 + u) * VV + j] = bj + part + oth;
        }
    }
}

// ---------------- launch ----------------
extern "C" void kernel_launch(void* const* d_in, const int* in_sizes, int n_in,
                              void* d_out, int out_size)
{
    const int*   x    = (const int*)d_in[0];
    const float* emb  = (const float*)d_in[1];
    const float* w_ih = (const float*)d_in[2];
    const float* w_hh = (const float*)d_in[3];
    const float* b_ih = (const float*)d_in[4];
    const float* b_hh = (const float*)d_in[5];
    const float* wqkv = (const float*)d_in[6];
    const float* bqkv = (const float*)d_in[7];
    const float* wo   = (const float*)d_in[8];
    const float* bo   = (const float*)d_in[9];
    const float* ln_g = (const float*)d_in[10];
    const float* ln_b = (const float*)d_in[11];
    const float* fc_w = (const float*)d_in[12];
    const float* fc_b = (const float*)d_in[13];
    float* out = (float*)d_out;

    float *bufA, *bufB, *qkvp, *attp;
    cudaGetSymbolAddress((void**)&bufA, g_bufA);
    cudaGetSymbolAddress((void**)&bufB, g_bufB);
    cudaGetSymbolAddress((void**)&qkvp, g_qkv);
    cudaGetSymbolAddress((void**)&attp, g_att);

    // launches: #1 table, #2 lstm, #3 qkv(l0), #4 attn(l0) <- profiled slot
    table_kernel<<<VV, G4H>>>(emb, w_ih, b_ih, b_hh);
    lstm_kernel<<<BB, 256>>>(x, w_hh, bufA);

    for (int l = 0; l < NLVL; l++) {
        const float* src = (l == 0) ? bufA : bufB;
        float*       dst = (l == 0) ? bufB : bufA;
        gemm_split_kernel<192, 1><<<NROWS / 64, 384>>>(
            src, wqkv + (size_t)l * 3 * HH * HH, bqkv + l * 3 * HH, qkvp);
        attn_kernel<<<TT * NHH, 64>>>(qkvp, attp);
        gemm_split_kernel<64, 2><<<NROWS / 64, 256>>>(
            attp, wo + (size_t)l * HH * HH, bo + l * HH, dst);
    }
    lnfc_kernel<<<NROWS / 32, 512>>>(bufA, ln_g, ln_b, fc_w, fc_b, out);
}